// round 6
// baseline (speedup 1.0000x reference)
#include <cuda_runtime.h>
#include <cstdint>

// ============================================================================
// Problem constants
// ============================================================================
#define MDIM   65536      // B*N = 2048*32
#define KDIM   1024       // model dim
#define NQKV   3072       // 3*DIM
#define NPROJ  1024
#define HEADS  16
#define HEAD_D 64
#define SEQ    32
#define BATCH  2048
#define KT     32         // k-tiles of 32 per K=1024

// ============================================================================
// Scratch (allocation-free rule: __device__ globals)
// ============================================================================
__device__ __align__(256) float g_qkv  [(size_t)MDIM * NQKV];   // 805 MB, fp32 row-major
__device__ __align__(256) float g_xs   [(size_t)MDIM * KDIM];   // 256 MB, tf32 tiled
__device__ __align__(256) float g_attns[(size_t)MDIM * KDIM];   // 256 MB, tf32 tiled
__device__ __align__(256) float g_wqs  [(size_t)NQKV * KDIM];   //  12 MB, tf32 tiled
__device__ __align__(256) float g_wps  [(size_t)NPROJ * KDIM];  //   4 MB, tf32 tiled

// ============================================================================
// Helpers — BASELINE PTX ONLY (compute_103 target: no tcgen05/TMEM)
// ============================================================================

// fp32 -> tf32 round-to-nearest (RNA). Unbiased rounding is correctness-
// critical: truncation bias over K=1024 would give ~1e-2 rel_err.
__device__ __forceinline__ float f2tf32(float x) {
    uint32_t y;
    asm("cvt.rna.tf32.f32 %0, %1;" : "=r"(y) : "f"(x));
    return __uint_as_float(y);
}

// m16n8k8 tf32 HMMA (sm_80 baseline instruction)
__device__ __forceinline__ void mma_tf32(float& c0, float& c1, float& c2, float& c3,
                                         float a0, float a1, float a2, float a3,
                                         float b0, float b1) {
    asm volatile(
        "mma.sync.aligned.m16n8k8.row.col.f32.tf32.tf32.f32 "
        "{%0,%1,%2,%3}, {%4,%5,%6,%7}, {%8,%9}, {%0,%1,%2,%3};"
        : "+f"(c0), "+f"(c1), "+f"(c2), "+f"(c3)
        : "r"(__float_as_uint(a0)), "r"(__float_as_uint(a1)),
          "r"(__float_as_uint(a2)), "r"(__float_as_uint(a3)),
          "r"(__float_as_uint(b0)), "r"(__float_as_uint(b1)));
}

// ----------------------------------------------------------------------------
// Tiled scratch layout (single source of truth):
//   matrix [R rows][K cols] -> tiles of 128 rows x 32 cols, 16 KB each,
//   tile id = (row>>7)*KT + (col>>5).
//   Within tile: r = row&127; c = col&31; ks = c>>3; j = c&7; lc = j&3; h = j>>2.
//   Physical float col p = ks*8 + 2*lc + h   (pairs (k, k+4) adjacent -> LDS.64)
//   Byte offset = r*128 + ((p<<2) ^ ((r&7)<<4))   (XOR swizzle pre-applied)
// cp.async then copies tile bytes 1:1 into smem; fragment LDS.64 reads are
// conflict-free per half-warp phase.
// ----------------------------------------------------------------------------
__device__ __forceinline__ size_t tiled_byte(int row, int col, int /*K*/) {
    int kt = col >> 5, c = col & 31;
    int ks = c >> 3, j = c & 7;
    int p  = ks * 8 + 2 * (j & 3) + (j >> 2);
    size_t tile = ((size_t)(row >> 7) * KT + kt) << 14;
    return tile + (size_t)((row & 127) << 7) + (uint32_t)(((p << 2)) ^ ((row & 7) << 4));
}

// ============================================================================
// Pre-pass: fp32 row-major -> tf32 tiled/permuted/swizzled scratch
// ============================================================================
__global__ void __launch_bounds__(256)
convert_tile_kernel(const float* __restrict__ src, float* __restrict__ dst,
                    int R, int K)
{
    size_t gid = (size_t)blockIdx.x * 256 + threadIdx.x;
    size_t total = ((size_t)R * K) >> 2;
    if (gid >= total) return;
    int kq  = K >> 2;
    int row = (int)(gid / kq);
    int c4  = (int)(gid % kq) << 2;
    float4 v = *(const float4*)(src + (size_t)row * K + c4);
    char* base = (char*)dst;
    float e[4] = {v.x, v.y, v.z, v.w};
#pragma unroll
    for (int i = 0; i < 4; ++i)
        *(float*)(base + tiled_byte(row, c4 + i, K)) = f2tf32(e[i]);
}

// ============================================================================
// GEMM: C[M,N] = At[M,K] @ Bt[N,K]^T + bias   (inputs pre-tiled tf32)
//   mma.sync m16n8k8, CTA tile 128x128, BK=32, 8 warps (2x4), warp 64x32.
//   3-stage cp.async pipeline, LDS.64 fragment loads, 1 sync/iter.
// ============================================================================
static constexpr int STAGES = 3;
static constexpr int STAGE_BYTES = 32768;            // A 16KB + B 16KB
static constexpr int GEMM_SMEM = STAGES * STAGE_BYTES;  // 96 KB

__global__ void __launch_bounds__(256, 2)
gemm_tc_kernel(const float* __restrict__ At, const float* __restrict__ Bt,
               const float* __restrict__ bias, float* __restrict__ C,
               int M, int N)
{
    extern __shared__ char smem[];
    uint32_t sb;
    asm("{ .reg .u64 t; cvta.to.shared.u64 t, %1; cvt.u32.u64 %0, t; }"
        : "=r"(sb) : "l"(smem));

    const int tid  = threadIdx.x;
    const int lane = tid & 31;
    const int w    = tid >> 5;
    const int wm   = w >> 2;     // 0..1
    const int wn   = w & 3;      // 0..3
    const int lg   = lane >> 2;  // 0..7
    const int lc   = lane & 3;   // 0..3

    // ---- grid swizzle: groups of 16 M-tiles, N-tile outer within group ----
    const int tiles_n = N >> 7;
    const int per = 16 * tiles_n;
    const int grp = blockIdx.x / per;
    const int r_  = blockIdx.x % per;
    const int mtile = grp * 16 + (r_ % 16);
    const int ntile = r_ / 16;
    const int m0 = mtile << 7, n0 = ntile << 7;

    // ---- producer: identity-copy one 16KB A tile + one 16KB B tile ----
    const char* Abase = (const char*)At + (((size_t)mtile * KT) << 14);
    const char* Bbase = (const char*)Bt + (((size_t)ntile * KT) << 14);
    const int cpo = tid * 64;  // 64 B per thread per tile

    auto issue = [&](int kt, int s) {
        const char* asrc = Abase + ((size_t)kt << 14) + cpo;
        const char* bsrc = Bbase + ((size_t)kt << 14) + cpo;
        uint32_t ad = sb + s * STAGE_BYTES + cpo;
        uint32_t bd = ad + 16384;
#pragma unroll
        for (int j = 0; j < 4; ++j) {
            asm volatile("cp.async.cg.shared.global [%0], [%1], 16;"
                         :: "r"(ad + j * 16), "l"(asrc + j * 16));
            asm volatile("cp.async.cg.shared.global [%0], [%1], 16;"
                         :: "r"(bd + j * 16), "l"(bsrc + j * 16));
        }
        asm volatile("cp.async.commit_group;" ::: "memory");
    };

    // ---- consumer address precompute ----
    // fragment pair (k, k+4) byte: r*128 + ((ks*32 + 8*lc) ^ (lg<<4))
    //   = [r*128 + (8*lc ^ ((lg&1)<<4))] + [(ks<<5) ^ ((lg>>1)<<5)]
    const uint32_t lo = (uint32_t)((8 * lc) ^ ((lg & 1) << 4));
    uint32_t sks[4];
#pragma unroll
    for (int ks = 0; ks < 4; ++ks) sks[ks] = (uint32_t)((ks ^ (lg >> 1)) << 5);
    uint32_t baseA[4], baseB[4];
#pragma unroll
    for (int mt = 0; mt < 4; ++mt)
        baseA[mt] = (uint32_t)((wm * 64 + mt * 16 + lg) << 7) + lo;
#pragma unroll
    for (int nt = 0; nt < 4; ++nt)
        baseB[nt] = (uint32_t)((wn * 32 + nt * 8 + lg) << 7) + 16384u + lo;

    float acc[4][4][4];
#pragma unroll
    for (int mt = 0; mt < 4; ++mt)
#pragma unroll
        for (int nt = 0; nt < 4; ++nt)
#pragma unroll
            for (int i = 0; i < 4; ++i) acc[mt][nt][i] = 0.f;

    issue(0, 0);
    issue(1, 1);

#pragma unroll 1
    for (int kt = 0; kt < KT; ++kt) {
        const int s = kt % 3;
        if (kt + 1 < KT) asm volatile("cp.async.wait_group 1;" ::: "memory");
        else             asm volatile("cp.async.wait_group 0;" ::: "memory");
        __syncthreads();
        if (kt + 2 < KT) issue(kt + 2, (kt + 2) % 3);

        const uint32_t sg = sb + (uint32_t)(s * STAGE_BYTES);
#pragma unroll
        for (int ks = 0; ks < 4; ++ks) {
            float2 fa0[4], fa1[4], fb[4];
#pragma unroll
            for (int mt = 0; mt < 4; ++mt) {
                uint32_t ad = sg + baseA[mt] + sks[ks];
                asm("ld.shared.v2.f32 {%0,%1}, [%2];"
                    : "=f"(fa0[mt].x), "=f"(fa0[mt].y) : "r"(ad));
                asm("ld.shared.v2.f32 {%0,%1}, [%2+1024];"      // row +8
                    : "=f"(fa1[mt].x), "=f"(fa1[mt].y) : "r"(ad));
            }
#pragma unroll
            for (int nt = 0; nt < 4; ++nt) {
                uint32_t bd = sg + baseB[nt] + sks[ks];
                asm("ld.shared.v2.f32 {%0,%1}, [%2];"
                    : "=f"(fb[nt].x), "=f"(fb[nt].y) : "r"(bd));
            }
#pragma unroll
            for (int mt = 0; mt < 4; ++mt)
#pragma unroll
                for (int nt = 0; nt < 4; ++nt)
                    mma_tf32(acc[mt][nt][0], acc[mt][nt][1],
                             acc[mt][nt][2], acc[mt][nt][3],
                             fa0[mt].x, fa1[mt].x, fa0[mt].y, fa1[mt].y,
                             fb[nt].x, fb[nt].y);
        }
    }

    // ---- epilogue: direct float2 global stores with bias ----
#pragma unroll
    for (int nt = 0; nt < 4; ++nt) {
        const int col = n0 + wn * 32 + nt * 8 + 2 * lc;
        const float b0 = __ldg(bias + col), b1 = __ldg(bias + col + 1);
#pragma unroll
        for (int mt = 0; mt < 4; ++mt) {
            const int row = m0 + wm * 64 + mt * 16 + lg;
            float2 v0 = make_float2(acc[mt][nt][0] + b0, acc[mt][nt][1] + b1);
            float2 v1 = make_float2(acc[mt][nt][2] + b0, acc[mt][nt][3] + b1);
            *(float2*)(C + (size_t)row * N + col)       = v0;
            *(float2*)(C + (size_t)(row + 8) * N + col) = v1;
        }
    }
}

// ============================================================================
// Attention: per (b,h): s = q k^T * 0.125 + rel_bias[h]; p = softmax; o = p v
// Output written directly as tf32 tiled scratch (free conversion for GEMM2).
// ============================================================================
__global__ void __launch_bounds__(128)
attn_kernel(const float* __restrict__ qkv, const float* __restrict__ rel_bias,
            float* __restrict__ attn_ts)
{
    __shared__ float q[32][65], k[32][65], v[32][65], s[32][33];
    const int bh = blockIdx.x;
    const int b = bh >> 4, h = bh & 15;
    const int tid = threadIdx.x;

    const size_t base = (size_t)b * SEQ * NQKV + (size_t)h * HEAD_D;
    for (int i = tid; i < SEQ * HEAD_D; i += 128) {
        int n = i >> 6, d = i & 63;
        size_t a = base + (size_t)n * NQKV + d;
        q[n][d] = qkv[a];
        k[n][d] = qkv[a + 1024];
        v[n][d] = qkv[a + 2048];
    }
    __syncthreads();

    {
        const int n  = tid >> 2;
        const int mb = tid & 3;
        const float* rbp = rel_bias + ((size_t)h * 32 + n) * 32;
#pragma unroll
        for (int j = 0; j < 8; ++j) {
            int m = mb + 4 * j;
            float acc = 0.f;
#pragma unroll
            for (int d = 0; d < 64; ++d) acc += q[n][d] * k[m][d];
            s[n][m] = acc * 0.125f + rbp[m];
        }
    }
    __syncthreads();

    {
        const int lane = tid & 31, w = tid >> 5;
        for (int rr = w * 8; rr < w * 8 + 8; ++rr) {
            float x = s[rr][lane];
            float mx = x;
#pragma unroll
            for (int off = 16; off > 0; off >>= 1)
                mx = fmaxf(mx, __shfl_xor_sync(0xFFFFFFFFu, mx, off));
            float e = __expf(x - mx);
            float sum = e;
#pragma unroll
            for (int off = 16; off > 0; off >>= 1)
                sum += __shfl_xor_sync(0xFFFFFFFFu, sum, off);
            s[rr][lane] = e / sum;
        }
    }
    __syncthreads();

    // out = p @ v, stored tf32-tiled at (row = b*32+n, col = h*64+d)
    char* base_ts = (char*)attn_ts;
    for (int i = tid; i < SEQ * HEAD_D; i += 128) {
        int n = i >> 6, d = i & 63;
        float acc = 0.f;
#pragma unroll
        for (int m = 0; m < 32; ++m) acc += s[n][m] * v[m][d];
        int row = b * SEQ + n;
        int col = h * HEAD_D + d;
        *(float*)(base_ts + tiled_byte(row, col, KDIM)) = f2tf32(acc);
    }
}

// ============================================================================
// Launcher
// ============================================================================
extern "C" void kernel_launch(void* const* d_in, const int* in_sizes, int n_in,
                              void* d_out, int out_size)
{
    const float* x      = (const float*)d_in[0];
    const float* W_qkv  = (const float*)d_in[1];
    const float* b_qkv  = (const float*)d_in[2];
    const float* W_proj = (const float*)d_in[3];
    const float* b_proj = (const float*)d_in[4];
    const float* rbias  = (const float*)d_in[5];
    float* out = (float*)d_out;

    void *p_qkv = nullptr, *p_xs = nullptr, *p_attns = nullptr,
         *p_wqs = nullptr, *p_wps = nullptr;
    cudaGetSymbolAddress(&p_qkv,   g_qkv);
    cudaGetSymbolAddress(&p_xs,    g_xs);
    cudaGetSymbolAddress(&p_attns, g_attns);
    cudaGetSymbolAddress(&p_wqs,   g_wqs);
    cudaGetSymbolAddress(&p_wps,   g_wps);

    cudaFuncSetAttribute(gemm_tc_kernel,
                         cudaFuncAttributeMaxDynamicSharedMemorySize, GEMM_SMEM);

    // Pre-pass: convert + tile (x, W_qkv, W_proj)
    convert_tile_kernel<<<((size_t)MDIM * KDIM / 4 + 255) / 256, 256>>>(
        x, (float*)p_xs, MDIM, KDIM);
    convert_tile_kernel<<<((size_t)NQKV * KDIM / 4 + 255) / 256, 256>>>(
        W_qkv, (float*)p_wqs, NQKV, KDIM);
    convert_tile_kernel<<<((size_t)NPROJ * KDIM / 4 + 255) / 256, 256>>>(
        W_proj, (float*)p_wps, NPROJ, KDIM);

    // GEMM1: qkv = x @ W_qkv^T + b_qkv  [65536 x 3072]
    gemm_tc_kernel<<<(MDIM / 128) * (NQKV / 128), 256, GEMM_SMEM>>>(
        (const float*)p_xs, (const float*)p_wqs, b_qkv, (float*)p_qkv, MDIM, NQKV);

    // Attention: 2048*16 (b,h) blocks -> tf32 tiled scratch
    attn_kernel<<<BATCH * HEADS, 128>>>(
        (const float*)p_qkv, rbias, (float*)p_attns);

    // GEMM2: out = attn @ W_proj^T + b_proj  [65536 x 1024]
    gemm_tc_kernel<<<(MDIM / 128) * (NPROJ / 128), 256, GEMM_SMEM>>>(
        (const float*)p_attns, (const float*)p_wps, b_proj, out, MDIM, NPROJ);
}